// round 13
// baseline (speedup 1.0000x reference)
#include <cuda_runtime.h>
#include <cuda_fp16.h>
#include <cstdint>

// WindowAttention: 4096 x 64 x 128, fp32 I/O. fp16 operands, fp32 accumulate,
// mma.m16n8k16. R13: 128 thr/CTA, 4 warps, 64x32 warp tiles. Weights read as
// B-fragments DIRECTLY from L2 (fp16 transposed by prep kernel) -> no smem W
// buffer, no staging stalls, no intra-GEMM1 barriers. Smem 70.7KB -> 3 CTAs/SM.

#define PXW 68   // X/Q/K/O pitch in words
#define PSW 36   // S pitch
#define PVW 36   // Vt pitch

#define OFF_X 0                      // 4352 words; S+Pm alias after GEMM1
#define OFF_Q (64*PXW)               // 4352
#define OFF_K (2*64*PXW)             // 8704
#define OFF_V (3*64*PXW)             // 13056, 128*PVW = 4608 words
#define OFF_S OFF_X
#define OFF_PM (OFF_X + 64*PSW)      // 2304..2816 inside X region
#define SMEM_WORDS (OFF_V + 128*PVW) // 17664
#define SMEM_BYTES (SMEM_WORDS*4)    // 70656 -> 3 CTAs/SM

__device__ __align__(16) __half g_wqkvT[384*128];
__device__ __align__(16) __half g_wprojT[128*128];

__global__ void prep_w(const float* __restrict__ wqkv, const float* __restrict__ wproj) {
    int n = blockIdx.x, k = threadIdx.x;
    if (n < 384) g_wqkvT[n*128+k] = __float2half_rn(wqkv[k*384+n]);
    else         g_wprojT[(n-384)*128+k] = __float2half_rn(wproj[k*128+(n-384)]);
}

__device__ __forceinline__ uint32_t h2u(float a, float b) {
    __half2 h = __floats2half2_rn(a, b);
    return *reinterpret_cast<uint32_t*>(&h);
}
__device__ __forceinline__ void mma16(float acc[4], uint32_t a0, uint32_t a1,
                                      uint32_t a2, uint32_t a3, uint32_t b0, uint32_t b1) {
    asm volatile(
        "mma.sync.aligned.m16n8k16.row.col.f32.f16.f16.f32 "
        "{%0,%1,%2,%3}, {%4,%5,%6,%7}, {%8,%9}, {%0,%1,%2,%3};\n"
        : "+f"(acc[0]), "+f"(acc[1]), "+f"(acc[2]), "+f"(acc[3])
        : "r"(a0), "r"(a1), "r"(a2), "r"(a3), "r"(b0), "r"(b1));
}
// one m16 A fragment at word ptr p (= base + row*pitch + kg*8 + t)
__device__ __forceinline__ void ldA4(uint32_t a[4], const uint32_t* p, int pitch) {
    a[0]=p[0]; a[1]=p[8*pitch]; a[2]=p[4]; a[3]=p[8*pitch+4];
}
// B fragment (b0,b1) for output col n, k-group kg, from global fp16 [n][k]
__device__ __forceinline__ void ldB(uint32_t& b0, uint32_t& b1,
                                    const __half* __restrict__ w, int n, int kg, int t) {
    const uint32_t* p = (const uint32_t*)(w + n*128) + kg*8 + t;
    b0 = __ldg(p); b1 = __ldg(p + 4);
}

__global__ void __launch_bounds__(128, 3)
win_attn_kernel(const float* __restrict__ x, const float* __restrict__ bqkv,
                const float* __restrict__ bproj, float* __restrict__ out)
{
    extern __shared__ uint32_t smw[];
    uint32_t* Xw = smw + OFF_X;
    uint32_t* Qw = smw + OFF_Q;   // reused for O
    uint32_t* Kw = smw + OFF_K;
    uint32_t* Vw = smw + OFF_V;
    uint32_t* Sw = smw + OFF_S;
    float*    Pm = (float*)(smw + OFF_PM);
    __half*   Vh = (__half*)Vw;

    const int tid = threadIdx.x, warp = tid >> 5, lane = tid & 31;
    const int g = lane >> 2, t = lane & 3;
    const int wc = warp;                    // 0..3: 32-col strip
    const int nbase = wc * 32, sbase = wc * 16;
    const float* xw = x + (size_t)blockIdx.x * 64 * 128;

    // ---- prologue: X fp32 -> half2 smem ----
    #pragma unroll
    for (int it = 0; it < 8; ++it) {
        int idx = tid + it*128, r = idx >> 4, q = idx & 15;
        const float4* s = (const float4*)(xw + r*128 + q*8);
        float4 fa = s[0], fb = s[1];
        *(uint4*)(Xw + r*PXW + q*4) =
            make_uint4(h2u(fa.x,fa.y), h2u(fa.z,fa.w), h2u(fb.x,fb.y), h2u(fb.z,fb.w));
    }
    __syncthreads();

    // ============ GEMM1: QKV = X @ Wqkv + b (3 chunks, NO internal syncs) ============
    #pragma unroll
    for (int c = 0; c < 3; ++c) {
        const __half* wsrc = g_wqkvT + c*128*128;
        float acc[4][4][4];
        #pragma unroll
        for (int m = 0; m < 4; ++m)
            #pragma unroll
            for (int n = 0; n < 4; ++n)
                acc[m][n][0]=acc[m][n][1]=acc[m][n][2]=acc[m][n][3]=0.f;

        #pragma unroll
        for (int kg = 0; kg < 8; ++kg) {
            uint32_t A[16];
            #pragma unroll
            for (int m = 0; m < 4; ++m)
                ldA4(A + m*4, Xw + (m*16+g)*PXW + kg*8 + t, PXW);
            #pragma unroll
            for (int nt = 0; nt < 4; ++nt) {
                uint32_t b0, b1;
                ldB(b0, b1, wsrc, nbase + nt*8 + g, kg, t);
                #pragma unroll
                for (int m = 0; m < 4; ++m)
                    mma16(acc[m][nt], A[m*4],A[m*4+1],A[m*4+2],A[m*4+3], b0, b1);
            }
        }

        if (c < 2) {     // Q or K: half2 rows
            uint32_t* D = (c == 0) ? Qw : Kw;
            #pragma unroll
            for (int m = 0; m < 4; ++m) {
                int r = m*16 + g;
                #pragma unroll
                for (int nt = 0; nt < 4; ++nt) {
                    int j = nbase + nt*8 + 2*t;
                    float b0 = __ldg(bqkv + c*128 + j), b1 = __ldg(bqkv + c*128 + j + 1);
                    int w = (nbase >> 1) + nt*4 + t;
                    D[r*PXW + w]     = h2u(acc[m][nt][0]+b0, acc[m][nt][1]+b1);
                    D[(r+8)*PXW + w] = h2u(acc[m][nt][2]+b0, acc[m][nt][3]+b1);
                }
            }
        } else {         // V: transposed scatter Vt[ch][tok]
            #pragma unroll
            for (int m = 0; m < 4; ++m) {
                int tok = m*16 + g;
                #pragma unroll
                for (int nt = 0; nt < 4; ++nt) {
                    int ch = nbase + nt*8 + 2*t;
                    float b0 = __ldg(bqkv + 256 + ch), b1 = __ldg(bqkv + 256 + ch + 1);
                    Vh[ch*(2*PVW) + tok]       = __float2half_rn(acc[m][nt][0]+b0);
                    Vh[(ch+1)*(2*PVW) + tok]   = __float2half_rn(acc[m][nt][1]+b1);
                    Vh[ch*(2*PVW) + tok+8]     = __float2half_rn(acc[m][nt][2]+b0);
                    Vh[(ch+1)*(2*PVW) + tok+8] = __float2half_rn(acc[m][nt][3]+b1);
                }
            }
        }
    }
    __syncthreads();    // Q/K/V complete (X now dead; S/Pm may reuse it)

    // ============ GEMM2: S = Q @ K^T (64x16 per warp) ============
    float sacc[4][2][4];
    #pragma unroll
    for (int m = 0; m < 4; ++m)
        #pragma unroll
        for (int n = 0; n < 2; ++n)
            sacc[m][n][0]=sacc[m][n][1]=sacc[m][n][2]=sacc[m][n][3]=0.f;

    #pragma unroll
    for (int kg = 0; kg < 8; ++kg) {
        uint32_t A[16];
        #pragma unroll
        for (int m = 0; m < 4; ++m)
            ldA4(A + m*4, Qw + (m*16+g)*PXW + kg*8 + t, PXW);
        #pragma unroll
        for (int nt = 0; nt < 2; ++nt) {
            const uint32_t* bp = Kw + (sbase + nt*8 + g)*PXW + kg*8 + t;
            uint32_t b0 = bp[0], b1 = bp[4];
            #pragma unroll
            for (int m = 0; m < 4; ++m)
                mma16(sacc[m][nt], A[m*4],A[m*4+1],A[m*4+2],A[m*4+3], b0, b1);
        }
    }

    // ---- softmax: each row spans all 4 warps (16 cols each) ----
    const float scale = 0.08838834764831844f;
    float mx[4][2];
    #pragma unroll
    for (int m = 0; m < 4; ++m) {
        mx[m][0] = -1e30f; mx[m][1] = -1e30f;
        #pragma unroll
        for (int n = 0; n < 2; ++n) {
            #pragma unroll
            for (int q = 0; q < 4; ++q) sacc[m][n][q] *= scale;
            mx[m][0] = fmaxf(mx[m][0], fmaxf(sacc[m][n][0], sacc[m][n][1]));
            mx[m][1] = fmaxf(mx[m][1], fmaxf(sacc[m][n][2], sacc[m][n][3]));
        }
    }
    #pragma unroll
    for (int m = 0; m < 4; ++m)
        #pragma unroll
        for (int h = 0; h < 2; ++h) {
            mx[m][h] = fmaxf(mx[m][h], __shfl_xor_sync(~0u, mx[m][h], 1));
            mx[m][h] = fmaxf(mx[m][h], __shfl_xor_sync(~0u, mx[m][h], 2));
        }
    if (t == 0)
        #pragma unroll
        for (int m = 0; m < 4; ++m)
            #pragma unroll
            for (int h = 0; h < 2; ++h)
                Pm[(m*16 + h*8 + g)*4 + wc] = mx[m][h];
    __syncthreads();
    #pragma unroll
    for (int m = 0; m < 4; ++m)
        #pragma unroll
        for (int h = 0; h < 2; ++h) {
            const float* p = Pm + (m*16 + h*8 + g)*4;
            mx[m][h] = fmaxf(fmaxf(p[0], p[1]), fmaxf(p[2], p[3]));
        }

    float sm[4][2];
    #pragma unroll
    for (int m = 0; m < 4; ++m) { sm[m][0] = 0.f; sm[m][1] = 0.f; }
    #pragma unroll
    for (int m = 0; m < 4; ++m)
        #pragma unroll
        for (int n = 0; n < 2; ++n) {
            sacc[m][n][0] = __expf(sacc[m][n][0] - mx[m][0]);
            sacc[m][n][1] = __expf(sacc[m][n][1] - mx[m][0]);
            sacc[m][n][2] = __expf(sacc[m][n][2] - mx[m][1]);
            sacc[m][n][3] = __expf(sacc[m][n][3] - mx[m][1]);
            sm[m][0] += sacc[m][n][0] + sacc[m][n][1];
            sm[m][1] += sacc[m][n][2] + sacc[m][n][3];
        }
    #pragma unroll
    for (int m = 0; m < 4; ++m)
        #pragma unroll
        for (int h = 0; h < 2; ++h) {
            sm[m][h] += __shfl_xor_sync(~0u, sm[m][h], 1);
            sm[m][h] += __shfl_xor_sync(~0u, sm[m][h], 2);
        }
    if (t == 0)
        #pragma unroll
        for (int m = 0; m < 4; ++m)
            #pragma unroll
            for (int h = 0; h < 2; ++h)
                Pm[512 + (m*16 + h*8 + g)*4 + wc] = sm[m][h];
    __syncthreads();
    float rs[4][2];
    #pragma unroll
    for (int m = 0; m < 4; ++m)
        #pragma unroll
        for (int h = 0; h < 2; ++h) {
            const float* p = Pm + 512 + (m*16 + h*8 + g)*4;
            rs[m][h] = 1.f / (p[0] + p[1] + p[2] + p[3]);
        }

    // P -> S half2 (S region aliases X; X dead)
    #pragma unroll
    for (int m = 0; m < 4; ++m) {
        int r = m*16 + g;
        #pragma unroll
        for (int nt = 0; nt < 2; ++nt) {
            int w = wc*8 + nt*4 + t;
            Sw[r*PSW + w]     = h2u(sacc[m][nt][0]*rs[m][0], sacc[m][nt][1]*rs[m][0]);
            Sw[(r+8)*PSW + w] = h2u(sacc[m][nt][2]*rs[m][1], sacc[m][nt][3]*rs[m][1]);
        }
    }
    __syncthreads();

    // ============ GEMM3: O = P @ Vt (64x32 per warp) ============
    float oacc[4][4][4];
    #pragma unroll
    for (int m = 0; m < 4; ++m)
        #pragma unroll
        for (int n = 0; n < 4; ++n)
            oacc[m][n][0]=oacc[m][n][1]=oacc[m][n][2]=oacc[m][n][3]=0.f;

    #pragma unroll
    for (int kg = 0; kg < 4; ++kg) {
        uint32_t A[16];
        #pragma unroll
        for (int m = 0; m < 4; ++m)
            ldA4(A + m*4, Sw + (m*16+g)*PSW + kg*8 + t, PSW);
        #pragma unroll
        for (int nt = 0; nt < 4; ++nt) {
            const uint32_t* bp = Vw + (nbase + nt*8 + g)*PVW + kg*8 + t;
            uint32_t b0 = bp[0], b1 = bp[4];
            #pragma unroll
            for (int m = 0; m < 4; ++m)
                mma16(oacc[m][nt], A[m*4],A[m*4+1],A[m*4+2],A[m*4+3], b0, b1);
        }
    }

    // O -> Qw (half2 rows; Q dead after GEMM2)
    #pragma unroll
    for (int m = 0; m < 4; ++m) {
        int r = m*16 + g;
        #pragma unroll
        for (int nt = 0; nt < 4; ++nt) {
            int w = (nbase >> 1) + nt*4 + t;
            Qw[r*PXW + w]     = h2u(oacc[m][nt][0], oacc[m][nt][1]);
            Qw[(r+8)*PXW + w] = h2u(oacc[m][nt][2], oacc[m][nt][3]);
        }
    }
    __syncthreads();

    // ============ GEMM4: out = O @ Wproj + b (B via LDG) ============
    float acc[4][4][4];
    #pragma unroll
    for (int m = 0; m < 4; ++m)
        #pragma unroll
        for (int n = 0; n < 4; ++n)
            acc[m][n][0]=acc[m][n][1]=acc[m][n][2]=acc[m][n][3]=0.f;

    #pragma unroll
    for (int kg = 0; kg < 8; ++kg) {
        uint32_t A[16];
        #pragma unroll
        for (int m = 0; m < 4; ++m)
            ldA4(A + m*4, Qw + (m*16+g)*PXW + kg*8 + t, PXW);
        #pragma unroll
        for (int nt = 0; nt < 4; ++nt) {
            uint32_t b0, b1;
            ldB(b0, b1, g_wprojT, nbase + nt*8 + g, kg, t);
            #pragma unroll
            for (int m = 0; m < 4; ++m)
                mma16(acc[m][nt], A[m*4],A[m*4+1],A[m*4+2],A[m*4+3], b0, b1);
        }
    }

    float* outw = out + (size_t)blockIdx.x * 64 * 128;
    #pragma unroll
    for (int m = 0; m < 4; ++m) {
        int r = m*16 + g;
        #pragma unroll
        for (int nt = 0; nt < 4; ++nt) {
            int j = nbase + nt*8 + 2*t;
            float b0 = __ldg(bproj + j), b1 = __ldg(bproj + j + 1);
            *(float2*)(outw + r*128 + j)     = make_float2(acc[m][nt][0]+b0, acc[m][nt][1]+b1);
            *(float2*)(outw + (r+8)*128 + j) = make_float2(acc[m][nt][2]+b0, acc[m][nt][3]+b1);
        }
    }
}

extern "C" void kernel_launch(void* const* d_in, const int* in_sizes, int n_in,
                              void* d_out, int out_size)
{
    const float* x     = (const float*)d_in[0];
    const float* wqkv  = (const float*)d_in[1];
    const float* bqkv  = (const float*)d_in[2];
    const float* wproj = (const float*)d_in[3];
    const float* bproj = (const float*)d_in[4];
    float* out = (float*)d_out;

    const int nwin = in_sizes[0] / (64 * 128);   // 4096

    prep_w<<<512, 128>>>(wqkv, wproj);
    cudaFuncSetAttribute(win_attn_kernel,
                         cudaFuncAttributeMaxDynamicSharedMemorySize, SMEM_BYTES);
    win_attn_kernel<<<nwin, 128, SMEM_BYTES>>>(x, bqkv, bproj, out);
}

// round 14
// speedup vs baseline: 1.2071x; 1.2071x over previous
#include <cuda_runtime.h>
#include <cuda_fp16.h>
#include <cstdint>

// WindowAttention: 4096 x 64 x 128, fp32 I/O. fp16 operands, fp32 accum,
// mma.m16n8k16. R14: 2 windows per CTA (256 thr, 8 warps = 2 win x 4 strips,
// 64x32 warp tiles). One weight staging serves both windows. Smem 172KB,
// 1 CTA/SM. Numerics identical to R12 (best=192.2us).

#define PXW 68   // X/Q/K/O pitch in words
#define PSW 36   // S pitch
#define PVW 36   // Vt pitch

#define OFF_X 0                      // 128 rows (2 windows); S+Pm alias per win
#define OFF_Q (128*PXW)              // 8704
#define OFF_K (256*PXW)              // 17408
#define OFF_V (384*PXW)              // 26112; 2 windows x 128ch x PVW = 9216
#define OFF_W (OFF_V + 2*128*PVW)    // 35328; 128*PXW = 8704
#define SMEM_WORDS (OFF_W + 128*PXW) // 44032
#define SMEM_BYTES (SMEM_WORDS*4)    // 176128 -> 1 CTA/SM

__device__ __align__(16) __half g_wqkvT[384*128];
__device__ __align__(16) __half g_wprojT[128*128];

__global__ void prep_w(const float* __restrict__ wqkv, const float* __restrict__ wproj) {
    int n = blockIdx.x, k = threadIdx.x;
    if (n < 384) g_wqkvT[n*128+k] = __float2half_rn(wqkv[k*384+n]);
    else         g_wprojT[(n-384)*128+k] = __float2half_rn(wproj[k*128+(n-384)]);
}

__device__ __forceinline__ uint32_t h2u(float a, float b) {
    __half2 h = __floats2half2_rn(a, b);
    return *reinterpret_cast<uint32_t*>(&h);
}
__device__ __forceinline__ void mma16(float acc[4], uint32_t a0, uint32_t a1,
                                      uint32_t a2, uint32_t a3, uint32_t b0, uint32_t b1) {
    asm volatile(
        "mma.sync.aligned.m16n8k16.row.col.f32.f16.f16.f32 "
        "{%0,%1,%2,%3}, {%4,%5,%6,%7}, {%8,%9}, {%0,%1,%2,%3};\n"
        : "+f"(acc[0]), "+f"(acc[1]), "+f"(acc[2]), "+f"(acc[3])
        : "r"(a0), "r"(a1), "r"(a2), "r"(a3), "r"(b0), "r"(b1));
}
__device__ __forceinline__ void bargrp(int id) {
    asm volatile("bar.sync %0, 128;" :: "r"(id) : "memory");
}
__device__ __forceinline__ void ldA4(uint32_t a[4], const uint32_t* p, int pitch) {
    a[0]=p[0]; a[1]=p[8*pitch]; a[2]=p[4]; a[3]=p[8*pitch+4];
}
// stage full 128x128 fp16 chunk [n][k] -> smem pitch PXW via cp.async 16B
__device__ __forceinline__ void stageW(uint32_t* Ww, const __half* __restrict__ src, int tid) {
    uint32_t base = (uint32_t)__cvta_generic_to_shared(Ww);
    #pragma unroll
    for (int it = 0; it < 8; ++it) {
        int idx = tid + it*256, n = idx >> 4, q = idx & 15;
        uint32_t dst = base + (uint32_t)(n*PXW + q*4)*4u;
        asm volatile("cp.async.ca.shared.global [%0], [%1], 16;"
                     :: "r"(dst), "l"(src + n*128 + q*8) : "memory");
    }
    asm volatile("cp.async.commit_group;\n\tcp.async.wait_group 0;" ::: "memory");
}

__global__ void __launch_bounds__(256, 1)
win_attn_kernel(const float* __restrict__ x, const float* __restrict__ bqkv,
                const float* __restrict__ bproj, float* __restrict__ out)
{
    extern __shared__ uint32_t smw[];
    uint32_t* Xw = smw + OFF_X;   // rows 0..127 = 2 windows
    uint32_t* Qw = smw + OFF_Q;   // reused for O
    uint32_t* Kw = smw + OFF_K;
    uint32_t* Ww = smw + OFF_W;

    const int tid = threadIdx.x, warp = tid >> 5, lane = tid & 31;
    const int g = lane >> 2, t = lane & 3;
    const int win = warp >> 2, wc = warp & 3;
    const int rb = win * 64;                 // row base of this warp's window
    const int nbase = wc * 32, sbase = wc * 16;

    // per-window aliases (S and Pm live in this window's X rows, dead then)
    uint32_t* Sw = smw + OFF_X + win * (64*PXW);
    float*    Pm = (float*)(Sw + 64*PSW);            // 1024 floats fit (2304+1024<4352)
    __half*   Vh = (__half*)(smw + OFF_V) + win * (128*2*PVW);

    const float* xw = x + (size_t)blockIdx.x * 128 * 128;   // 2 windows contiguous

    // ---- prologue: X (128 rows) fp32 -> half2 smem ----
    #pragma unroll
    for (int it = 0; it < 8; ++it) {
        int idx = tid + it*256, r = idx >> 4, q = idx & 15;
        const float4* s = (const float4*)(xw + r*128 + q*8);
        float4 fa = s[0], fb = s[1];
        *(uint4*)(Xw + r*PXW + q*4) =
            make_uint4(h2u(fa.x,fa.y), h2u(fa.z,fa.w), h2u(fb.x,fb.y), h2u(fb.z,fb.w));
    }
    stageW(Ww, g_wqkvT, tid);
    __syncthreads();

    // ============ GEMM1: QKV = X @ Wqkv + b (3 chunks of 128 cols) ============
    #pragma unroll
    for (int c = 0; c < 3; ++c) {
        float acc[4][4][4];
        #pragma unroll
        for (int m = 0; m < 4; ++m)
            #pragma unroll
            for (int n = 0; n < 4; ++n)
                acc[m][n][0]=acc[m][n][1]=acc[m][n][2]=acc[m][n][3]=0.f;

        #pragma unroll
        for (int kg = 0; kg < 8; ++kg) {
            uint32_t A[16];
            #pragma unroll
            for (int m = 0; m < 4; ++m)
                ldA4(A + m*4, Xw + (rb + m*16+g)*PXW + kg*8 + t, PXW);
            #pragma unroll
            for (int nt = 0; nt < 4; ++nt) {
                const uint32_t* bp = Ww + (nbase + nt*8 + g)*PXW + kg*8 + t;
                uint32_t b0 = bp[0], b1 = bp[4];
                #pragma unroll
                for (int m = 0; m < 4; ++m)
                    mma16(acc[m][nt], A[m*4],A[m*4+1],A[m*4+2],A[m*4+3], b0, b1);
            }
        }

        if (c < 2) {     // Q or K rows (window-local rows rb+r)
            uint32_t* D = (c == 0) ? Qw : Kw;
            #pragma unroll
            for (int m = 0; m < 4; ++m) {
                int r = rb + m*16 + g;
                #pragma unroll
                for (int nt = 0; nt < 4; ++nt) {
                    int j = nbase + nt*8 + 2*t;
                    float b0 = __ldg(bqkv + c*128 + j), b1 = __ldg(bqkv + c*128 + j + 1);
                    int w = (nbase >> 1) + nt*4 + t;
                    D[r*PXW + w]     = h2u(acc[m][nt][0]+b0, acc[m][nt][1]+b1);
                    D[(r+8)*PXW + w] = h2u(acc[m][nt][2]+b0, acc[m][nt][3]+b1);
                }
            }
        } else {         // V: transposed scatter Vt[ch][tok] (own window)
            #pragma unroll
            for (int m = 0; m < 4; ++m) {
                int tok = m*16 + g;
                #pragma unroll
                for (int nt = 0; nt < 4; ++nt) {
                    int ch = nbase + nt*8 + 2*t;
                    float b0 = __ldg(bqkv + 256 + ch), b1 = __ldg(bqkv + 256 + ch + 1);
                    Vh[ch*(2*PVW) + tok]       = __float2half_rn(acc[m][nt][0]+b0);
                    Vh[(ch+1)*(2*PVW) + tok]   = __float2half_rn(acc[m][nt][1]+b1);
                    Vh[ch*(2*PVW) + tok+8]     = __float2half_rn(acc[m][nt][2]+b0);
                    Vh[(ch+1)*(2*PVW) + tok+8] = __float2half_rn(acc[m][nt][3]+b1);
                }
            }
        }
        __syncthreads();
        if (c < 2) { stageW(Ww, g_wqkvT + (c+1)*128*128, tid); __syncthreads(); }
    }

    // ============ GEMM2: S = Q @ K^T (64x16 per warp, own window) ============
    float sacc[4][2][4];
    #pragma unroll
    for (int m = 0; m < 4; ++m)
        #pragma unroll
        for (int n = 0; n < 2; ++n)
            sacc[m][n][0]=sacc[m][n][1]=sacc[m][n][2]=sacc[m][n][3]=0.f;

    #pragma unroll
    for (int kg = 0; kg < 8; ++kg) {
        uint32_t A[16];
        #pragma unroll
        for (int m = 0; m < 4; ++m)
            ldA4(A + m*4, Qw + (rb + m*16+g)*PXW + kg*8 + t, PXW);
        #pragma unroll
        for (int nt = 0; nt < 2; ++nt) {
            const uint32_t* bp = Kw + (rb + sbase + nt*8 + g)*PXW + kg*8 + t;
            uint32_t b0 = bp[0], b1 = bp[4];
            #pragma unroll
            for (int m = 0; m < 4; ++m)
                mma16(sacc[m][nt], A[m*4],A[m*4+1],A[m*4+2],A[m*4+3], b0, b1);
        }
    }

    // ---- softmax: row spans the 4 warps of this window ----
    const float scale = 0.08838834764831844f;
    const int bid = 1 + win;
    float mx[4][2];
    #pragma unroll
    for (int m = 0; m < 4; ++m) {
        mx[m][0] = -1e30f; mx[m][1] = -1e30f;
        #pragma unroll
        for (int n = 0; n < 2; ++n) {
            #pragma unroll
            for (int q = 0; q < 4; ++q) sacc[m][n][q] *= scale;
            mx[m][0] = fmaxf(mx[m][0], fmaxf(sacc[m][n][0], sacc[m][n][1]));
            mx[m][1] = fmaxf(mx[m][1], fmaxf(sacc[m][n][2], sacc[m][n][3]));
        }
    }
    #pragma unroll
    for (int m = 0; m < 4; ++m)
        #pragma unroll
        for (int h = 0; h < 2; ++h) {
            mx[m][h] = fmaxf(mx[m][h], __shfl_xor_sync(~0u, mx[m][h], 1));
            mx[m][h] = fmaxf(mx[m][h], __shfl_xor_sync(~0u, mx[m][h], 2));
        }
    if (t == 0)
        #pragma unroll
        for (int m = 0; m < 4; ++m)
            #pragma unroll
            for (int h = 0; h < 2; ++h)
                Pm[(m*16 + h*8 + g)*4 + wc] = mx[m][h];
    bargrp(bid);
    #pragma unroll
    for (int m = 0; m < 4; ++m)
        #pragma unroll
        for (int h = 0; h < 2; ++h) {
            const float* p = Pm + (m*16 + h*8 + g)*4;
            mx[m][h] = fmaxf(fmaxf(p[0], p[1]), fmaxf(p[2], p[3]));
        }

    float sm[4][2];
    #pragma unroll
    for (int m = 0; m < 4; ++m) { sm[m][0] = 0.f; sm[m][1] = 0.f; }
    #pragma unroll
    for (int m = 0; m < 4; ++m)
        #pragma unroll
        for (int n = 0; n < 2; ++n) {
            sacc[m][n][0] = __expf(sacc[m][n][0] - mx[m][0]);
            sacc[m][n][1] = __expf(sacc[m][n][1] - mx[m][0]);
            sacc[m][n][2] = __expf(sacc[m][n][2] - mx[m][1]);
            sacc[m][n][3] = __expf(sacc[m][n][3] - mx[m][1]);
            sm[m][0] += sacc[m][n][0] + sacc[m][n][1];
            sm[m][1] += sacc[m][n][2] + sacc[m][n][3];
        }
    #pragma unroll
    for (int m = 0; m < 4; ++m)
        #pragma unroll
        for (int h = 0; h < 2; ++h) {
            sm[m][h] += __shfl_xor_sync(~0u, sm[m][h], 1);
            sm[m][h] += __shfl_xor_sync(~0u, sm[m][h], 2);
        }
    if (t == 0)
        #pragma unroll
        for (int m = 0; m < 4; ++m)
            #pragma unroll
            for (int h = 0; h < 2; ++h)
                Pm[512 + (m*16 + h*8 + g)*4 + wc] = sm[m][h];
    bargrp(bid);
    float rs[4][2];
    #pragma unroll
    for (int m = 0; m < 4; ++m)
        #pragma unroll
        for (int h = 0; h < 2; ++h) {
            const float* p = Pm + 512 + (m*16 + h*8 + g)*4;
            rs[m][h] = 1.f / (p[0] + p[1] + p[2] + p[3]);
        }

    // P -> S half2 (S aliases own window's X rows; X dead)
    #pragma unroll
    for (int m = 0; m < 4; ++m) {
        int r = m*16 + g;
        #pragma unroll
        for (int nt = 0; nt < 2; ++nt) {
            int w = wc*8 + nt*4 + t;
            Sw[r*PSW + w]     = h2u(sacc[m][nt][0]*rs[m][0], sacc[m][nt][1]*rs[m][0]);
            Sw[(r+8)*PSW + w] = h2u(sacc[m][nt][2]*rs[m][1], sacc[m][nt][3]*rs[m][1]);
        }
    }
    bargrp(bid);

    // ============ GEMM3: O = P @ Vt (64x32 per warp, own window) ============
    float oacc[4][4][4];
    #pragma unroll
    for (int m = 0; m < 4; ++m)
        #pragma unroll
        for (int n = 0; n < 4; ++n)
            oacc[m][n][0]=oacc[m][n][1]=oacc[m][n][2]=oacc[m][n][3]=0.f;

    const uint32_t* Vwp = (const uint32_t*)Vh;
    #pragma unroll
    for (int kg = 0; kg < 4; ++kg) {
        uint32_t A[16];
        #pragma unroll
        for (int m = 0; m < 4; ++m)
            ldA4(A + m*4, Sw + (m*16+g)*PSW + kg*8 + t, PSW);
        #pragma unroll
        for (int nt = 0; nt < 4; ++nt) {
            const uint32_t* bp = Vwp + (nbase + nt*8 + g)*PVW + kg*8 + t;
            uint32_t b0 = bp[0], b1 = bp[4];
            #pragma unroll
            for (int m = 0; m < 4; ++m)
                mma16(oacc[m][nt], A[m*4],A[m*4+1],A[m*4+2],A[m*4+3], b0, b1);
        }
    }

    // O -> Qw (own window rows; Q dead after GEMM2)
    #pragma unroll
    for (int m = 0; m < 4; ++m) {
        int r = rb + m*16 + g;
        #pragma unroll
        for (int nt = 0; nt < 4; ++nt) {
            int w = (nbase >> 1) + nt*4 + t;
            Qw[r*PXW + w]     = h2u(oacc[m][nt][0], oacc[m][nt][1]);
            Qw[(r+8)*PXW + w] = h2u(oacc[m][nt][2], oacc[m][nt][3]);
        }
    }
    __syncthreads();                   // both windows done with S/V reads
    stageW(Ww, g_wprojT, tid);
    __syncthreads();

    // ============ GEMM4: out = O @ Wproj + b ============
    float acc[4][4][4];
    #pragma unroll
    for (int m = 0; m < 4; ++m)
        #pragma unroll
        for (int n = 0; n < 4; ++n)
            acc[m][n][0]=acc[m][n][1]=acc[m][n][2]=acc[m][n][3]=0.f;

    #pragma unroll
    for (int kg = 0; kg < 8; ++kg) {
        uint32_t A[16];
        #pragma unroll
        for (int m = 0; m < 4; ++m)
            ldA4(A + m*4, Qw + (rb + m*16+g)*PXW + kg*8 + t, PXW);
        #pragma unroll
        for (int nt = 0; nt < 4; ++nt) {
            const uint32_t* bp = Ww + (nbase + nt*8 + g)*PXW + kg*8 + t;
            uint32_t b0 = bp[0], b1 = bp[4];
            #pragma unroll
            for (int m = 0; m < 4; ++m)
                mma16(acc[m][nt], A[m*4],A[m*4+1],A[m*4+2],A[m*4+3], b0, b1);
        }
    }

    float* outw = out + (size_t)blockIdx.x * 128 * 128;
    #pragma unroll
    for (int m = 0; m < 4; ++m) {
        int r = rb + m*16 + g;
        #pragma unroll
        for (int nt = 0; nt < 4; ++nt) {
            int j = nbase + nt*8 + 2*t;
            float b0 = __ldg(bproj + j), b1 = __ldg(bproj + j + 1);
            *(float2*)(outw + r*128 + j)     = make_float2(acc[m][nt][0]+b0, acc[m][nt][1]+b1);
            *(float2*)(outw + (r+8)*128 + j) = make_float2(acc[m][nt][2]+b0, acc[m][nt][3]+b1);
        }
    }
}

extern "C" void kernel_launch(void* const* d_in, const int* in_sizes, int n_in,
                              void* d_out, int out_size)
{
    const float* x     = (const float*)d_in[0];
    const float* wqkv  = (const float*)d_in[1];
    const float* bqkv  = (const float*)d_in[2];
    const float* wproj = (const float*)d_in[3];
    const float* bproj = (const float*)d_in[4];
    float* out = (float*)d_out;

    const int nwin = in_sizes[0] / (64 * 128);   // 4096

    prep_w<<<512, 128>>>(wqkv, wproj);
    cudaFuncSetAttribute(win_attn_kernel,
                         cudaFuncAttributeMaxDynamicSharedMemorySize, SMEM_BYTES);
    win_attn_kernel<<<nwin / 2, 256, SMEM_BYTES>>>(x, bqkv, bproj, out);
}

// round 15
// speedup vs baseline: 1.2707x; 1.0526x over previous
#include <cuda_runtime.h>
#include <cuda_fp16.h>
#include <cstdint>

// WindowAttention: 4096 x 64 x 128, fp32 I/O. fp16 operands, fp32 accum,
// mma.m16n8k16. R15 = R12 (best, 192us) + fragment-native layouts:
//  - Q/S/O in "qtiles": A-frag = 2x LDS.64, epilogue = 1x STS.64 (conflict-free)
//  - W in "btiles" (prep kernel emits layout): B-frag = 1x LDS.64, flat staging
// X/K/Vt keep R12 linear layouts. Same wavefronts, ~30% fewer smem instrs.
// 128 thr/CTA, 4 warps, 64x32 warp tiles, 2 CTAs/SM.

#define PXW 68   // X/K linear pitch in words
#define PVW 36   // Vt linear pitch

#define OFF_X 0                      // 4352 w (S qtiles + Pm alias after GEMM1)
#define OFF_Q 4352                   // Q/O qtiles [m=4][kg=8]*128w = 4096 w
#define OFF_K 8448                   // 4352 w
#define OFF_V 12800                  // 4608 w
#define OFF_W 17408                  // W btiles [n8=16][kg=8]*64w = 8192 w
#define OFF_S OFF_X                  // S qtiles [m=4][kg=4]*128w = 2048 w
#define OFF_PM (OFF_X + 2048)        // 768 floats used
#define SMEM_WORDS 25600
#define SMEM_BYTES (SMEM_WORDS*4)    // 102400 -> 2 CTAs/SM

// weights pre-packed into btile layout: [n8][kg][i=g*4+t][slot] (uint32 words)
__device__ __align__(16) uint32_t g_wqkvB[3*8192];
__device__ __align__(16) uint32_t g_wprojB[8192];

__global__ void prep_w(const float* __restrict__ wqkv, const float* __restrict__ wproj) {
    int b = blockIdx.x;          // global output col (0..383 qkv, 384..511 proj)
    int k = threadIdx.x * 2;     // 64 threads, k even
    int wi = (k >> 1) & 7;
    uint32_t off = (uint32_t)((((b & 127) >> 3) * 8 + (k >> 4)) * 64
                 + (((b & 7) * 4 + (wi & 3)) * 2) + (wi >> 2));
    if (b < 384) {
        __half2 h = __floats2half2_rn(wqkv[k*384 + b], wqkv[(k+1)*384 + b]);
        g_wqkvB[(b >> 7)*8192 + off] = *reinterpret_cast<uint32_t*>(&h);
    } else {
        int n = b - 384;
        uint32_t o2 = (uint32_t)(((n >> 3) * 8 + (k >> 4)) * 64
                    + ((n & 7) * 4 + (wi & 3)) * 2 + (wi >> 2));
        __half2 h = __floats2half2_rn(wproj[k*128 + n], wproj[(k+1)*128 + n]);
        g_wprojB[o2] = *reinterpret_cast<uint32_t*>(&h);
    }
}

__device__ __forceinline__ uint32_t h2u(float a, float b) {
    __half2 h = __floats2half2_rn(a, b);
    return *reinterpret_cast<uint32_t*>(&h);
}
__device__ __forceinline__ void mma16(float acc[4], uint32_t a0, uint32_t a1,
                                      uint32_t a2, uint32_t a3, uint32_t b0, uint32_t b1) {
    asm volatile(
        "mma.sync.aligned.m16n8k16.row.col.f32.f16.f16.f32 "
        "{%0,%1,%2,%3}, {%4,%5,%6,%7}, {%8,%9}, {%0,%1,%2,%3};\n"
        : "+f"(acc[0]), "+f"(acc[1]), "+f"(acc[2]), "+f"(acc[3])
        : "r"(a0), "r"(a1), "r"(a2), "r"(a3), "r"(b0), "r"(b1));
}
// A fragment from qtile region (KG = #k16 groups): 2x LDS.64
__device__ __forceinline__ void ldAq(uint32_t a[4], const uint32_t* base,
                                     int m, int kg, int KG, int i) {
    const uint2* p = (const uint2*)(base + (m*KG + kg)*128) + i;
    uint2 lo = p[0], hi = p[32];
    a[0]=lo.x; a[1]=lo.y; a[2]=hi.x; a[3]=hi.y;
}
// linear A fragment (X): 4x LDS.32 (unchanged from R12)
__device__ __forceinline__ void ldA4(uint32_t a[4], const uint32_t* p, int pitch) {
    a[0]=p[0]; a[1]=p[8*pitch]; a[2]=p[4]; a[3]=p[8*pitch+4];
}
// stage 8192-word btile chunk (flat copy) via cp.async 16B
__device__ __forceinline__ void stageW(uint32_t* Ww, const uint32_t* __restrict__ src, int tid) {
    uint32_t base = (uint32_t)__cvta_generic_to_shared(Ww);
    #pragma unroll
    for (int it = 0; it < 16; ++it) {
        int idx = tid + it*128;
        asm volatile("cp.async.ca.shared.global [%0], [%1], 16;"
                     :: "r"(base + (uint32_t)idx*16u), "l"(src + idx*4) : "memory");
    }
    asm volatile("cp.async.commit_group;\n\tcp.async.wait_group 0;" ::: "memory");
}

__global__ void __launch_bounds__(128, 2)
win_attn_kernel(const float* __restrict__ x, const float* __restrict__ bqkv,
                const float* __restrict__ bproj, float* __restrict__ out)
{
    extern __shared__ uint32_t smw[];
    uint32_t* Xw = smw + OFF_X;
    uint32_t* Qb = smw + OFF_Q;   // qtiles; reused for O
    uint32_t* Kw = smw + OFF_K;
    uint32_t* Vw = smw + OFF_V;
    uint32_t* Wb = smw + OFF_W;
    uint32_t* Sb = smw + OFF_S;
    float*    Pm = (float*)(smw + OFF_PM);
    __half*   Vh = (__half*)Vw;

    const int tid = threadIdx.x, warp = tid >> 5, lane = tid & 31;
    const int g = lane >> 2, t = lane & 3;
    const int i4 = g*4 + t;
    const int wc = warp;
    const int nbase = wc * 32, sbase = wc * 16;
    const float* xw = x + (size_t)blockIdx.x * 64 * 128;

    // ---- prologue: X fp32 -> half2 smem (linear); W chunk0 btiles ----
    #pragma unroll
    for (int it = 0; it < 8; ++it) {
        int idx = tid + it*128, r = idx >> 4, q = idx & 15;
        const float4* s = (const float4*)(xw + r*128 + q*8);
        float4 fa = s[0], fb = s[1];
        *(uint4*)(Xw + r*PXW + q*4) =
            make_uint4(h2u(fa.x,fa.y), h2u(fa.z,fa.w), h2u(fb.x,fb.y), h2u(fb.z,fb.w));
    }
    stageW(Wb, g_wqkvB, tid);
    __syncthreads();

    // ============ GEMM1: QKV = X @ Wqkv + b (3 chunks of 128 cols) ============
    #pragma unroll
    for (int c = 0; c < 3; ++c) {
        float acc[4][4][4];
        #pragma unroll
        for (int m = 0; m < 4; ++m)
            #pragma unroll
            for (int n = 0; n < 4; ++n)
                acc[m][n][0]=acc[m][n][1]=acc[m][n][2]=acc[m][n][3]=0.f;

        #pragma unroll
        for (int kg = 0; kg < 8; ++kg) {
            uint32_t A[16];
            #pragma unroll
            for (int m = 0; m < 4; ++m)
                ldA4(A + m*4, Xw + (m*16+g)*PXW + kg*8 + t, PXW);
            #pragma unroll
            for (int nt = 0; nt < 4; ++nt) {
                uint2 b = *(const uint2*)(Wb + ((wc*4+nt)*8 + kg)*64 + i4*2);
                #pragma unroll
                for (int m = 0; m < 4; ++m)
                    mma16(acc[m][nt], A[m*4],A[m*4+1],A[m*4+2],A[m*4+3], b.x, b.y);
            }
        }

        if (c == 0) {    // Q -> qtiles: 1 STS.64 per (m,nt)
            #pragma unroll
            for (int m = 0; m < 4; ++m)
                #pragma unroll
                for (int nt = 0; nt < 4; ++nt) {
                    int j = nbase + nt*8 + 2*t;
                    float b0 = __ldg(bqkv + j), b1 = __ldg(bqkv + j + 1);
                    int kg = wc*2 + (nt >> 1);
                    *(uint2*)(Qb + (m*8+kg)*128 + (nt&1)*64 + i4*2) =
                        make_uint2(h2u(acc[m][nt][0]+b0, acc[m][nt][1]+b1),
                                   h2u(acc[m][nt][2]+b0, acc[m][nt][3]+b1));
                }
        } else if (c == 1) {   // K -> linear rows (unchanged)
            #pragma unroll
            for (int m = 0; m < 4; ++m) {
                int r = m*16 + g;
                #pragma unroll
                for (int nt = 0; nt < 4; ++nt) {
                    int j = nbase + nt*8 + 2*t;
                    float b0 = __ldg(bqkv + 128 + j), b1 = __ldg(bqkv + 128 + j + 1);
                    int w = (nbase >> 1) + nt*4 + t;
                    Kw[r*PXW + w]     = h2u(acc[m][nt][0]+b0, acc[m][nt][1]+b1);
                    Kw[(r+8)*PXW + w] = h2u(acc[m][nt][2]+b0, acc[m][nt][3]+b1);
                }
            }
        } else {         // V -> transposed scatter Vt[ch][tok] (unchanged)
            #pragma unroll
            for (int m = 0; m < 4; ++m) {
                int tok = m*16 + g;
                #pragma unroll
                for (int nt = 0; nt < 4; ++nt) {
                    int ch = nbase + nt*8 + 2*t;
                    float b0 = __ldg(bqkv + 256 + ch), b1 = __ldg(bqkv + 256 + ch + 1);
                    Vh[ch*(2*PVW) + tok]       = __float2half_rn(acc[m][nt][0]+b0);
                    Vh[(ch+1)*(2*PVW) + tok]   = __float2half_rn(acc[m][nt][1]+b1);
                    Vh[ch*(2*PVW) + tok+8]     = __float2half_rn(acc[m][nt][2]+b0);
                    Vh[(ch+1)*(2*PVW) + tok+8] = __float2half_rn(acc[m][nt][3]+b1);
                }
            }
        }
        __syncthreads();
        if (c < 2) { stageW(Wb, g_wqkvB + (c+1)*8192, tid); __syncthreads(); }
    }

    // ============ GEMM2: S = Q @ K^T (64x16 per warp) ============
    float sacc[4][2][4];
    #pragma unroll
    for (int m = 0; m < 4; ++m)
        #pragma unroll
        for (int n = 0; n < 2; ++n)
            sacc[m][n][0]=sacc[m][n][1]=sacc[m][n][2]=sacc[m][n][3]=0.f;

    #pragma unroll
    for (int kg = 0; kg < 8; ++kg) {
        uint32_t A[16];
        #pragma unroll
        for (int m = 0; m < 4; ++m)
            ldAq(A + m*4, Qb, m, kg, 8, i4);
        #pragma unroll
        for (int nt = 0; nt < 2; ++nt) {
            const uint32_t* bp = Kw + (sbase + nt*8 + g)*PXW + kg*8 + t;
            uint32_t b0 = bp[0], b1 = bp[4];
            #pragma unroll
            for (int m = 0; m < 4; ++m)
                mma16(sacc[m][nt], A[m*4],A[m*4+1],A[m*4+2],A[m*4+3], b0, b1);
        }
    }

    // ---- softmax: each row spans all 4 warps (16 cols each) ----
    const float scale = 0.08838834764831844f;
    float mx[4][2];
    #pragma unroll
    for (int m = 0; m < 4; ++m) {
        mx[m][0] = -1e30f; mx[m][1] = -1e30f;
        #pragma unroll
        for (int n = 0; n < 2; ++n) {
            #pragma unroll
            for (int q = 0; q < 4; ++q) sacc[m][n][q] *= scale;
            mx[m][0] = fmaxf(mx[m][0], fmaxf(sacc[m][n][0], sacc[m][n][1]));
            mx[m][1] = fmaxf(mx[m][1], fmaxf(sacc[m][n][2], sacc[m][n][3]));
        }
    }
    #pragma unroll
    for (int m = 0; m < 4; ++m)
        #pragma unroll
        for (int h = 0; h < 2; ++h) {
            mx[m][h] = fmaxf(mx[m][h], __shfl_xor_sync(~0u, mx[m][h], 1));
            mx[m][h] = fmaxf(mx[m][h], __shfl_xor_sync(~0u, mx[m][h], 2));
        }
    if (t == 0)
        #pragma unroll
        for (int m = 0; m < 4; ++m)
            #pragma unroll
            for (int h = 0; h < 2; ++h)
                Pm[(m*16 + h*8 + g)*4 + wc] = mx[m][h];
    __syncthreads();
    #pragma unroll
    for (int m = 0; m < 4; ++m)
        #pragma unroll
        for (int h = 0; h < 2; ++h) {
            const float* p = Pm + (m*16 + h*8 + g)*4;
            mx[m][h] = fmaxf(fmaxf(p[0], p[1]), fmaxf(p[2], p[3]));
        }

    float sm[4][2];
    #pragma unroll
    for (int m = 0; m < 4; ++m) { sm[m][0] = 0.f; sm[m][1] = 0.f; }
    #pragma unroll
    for (int m = 0; m < 4; ++m)
        #pragma unroll
        for (int n = 0; n < 2; ++n) {
            sacc[m][n][0] = __expf(sacc[m][n][0] - mx[m][0]);
            sacc[m][n][1] = __expf(sacc[m][n][1] - mx[m][0]);
            sacc[m][n][2] = __expf(sacc[m][n][2] - mx[m][1]);
            sacc[m][n][3] = __expf(sacc[m][n][3] - mx[m][1]);
            sm[m][0] += sacc[m][n][0] + sacc[m][n][1];
            sm[m][1] += sacc[m][n][2] + sacc[m][n][3];
        }
    #pragma unroll
    for (int m = 0; m < 4; ++m)
        #pragma unroll
        for (int h = 0; h < 2; ++h) {
            sm[m][h] += __shfl_xor_sync(~0u, sm[m][h], 1);
            sm[m][h] += __shfl_xor_sync(~0u, sm[m][h], 2);
        }
    if (t == 0)
        #pragma unroll
        for (int m = 0; m < 4; ++m)
            #pragma unroll
            for (int h = 0; h < 2; ++h)
                Pm[512 + (m*16 + h*8 + g)*4 + wc] = sm[m][h];
    __syncthreads();
    float rs[4][2];
    #pragma unroll
    for (int m = 0; m < 4; ++m)
        #pragma unroll
        for (int h = 0; h < 2; ++h) {
            const float* p = Pm + 512 + (m*16 + h*8 + g)*4;
            rs[m][h] = 1.f / (p[0] + p[1] + p[2] + p[3]);
        }

    // P -> S qtiles: 1 STS.64 per (m,nt)  (S aliases X; X dead)
    #pragma unroll
    for (int m = 0; m < 4; ++m)
        #pragma unroll
        for (int nt = 0; nt < 2; ++nt) {
            *(uint2*)(Sb + (m*4+wc)*128 + nt*64 + i4*2) =
                make_uint2(h2u(sacc[m][nt][0]*rs[m][0], sacc[m][nt][1]*rs[m][0]),
                           h2u(sacc[m][nt][2]*rs[m][1], sacc[m][nt][3]*rs[m][1]));
        }
    __syncthreads();

    // ============ GEMM3: O = P @ Vt (64x32 per warp) ============
    float oacc[4][4][4];
    #pragma unroll
    for (int m = 0; m < 4; ++m)
        #pragma unroll
        for (int n = 0; n < 4; ++n)
            oacc[m][n][0]=oacc[m][n][1]=oacc[m][n][2]=oacc[m][n][3]=0.f;

    #pragma unroll
    for (int kg = 0; kg < 4; ++kg) {
        uint32_t A[16];
        #pragma unroll
        for (int m = 0; m < 4; ++m)
            ldAq(A + m*4, Sb, m, kg, 4, i4);
        #pragma unroll
        for (int nt = 0; nt < 4; ++nt) {
            const uint32_t* bp = Vw + (nbase + nt*8 + g)*PVW + kg*8 + t;
            uint32_t b0 = bp[0], b1 = bp[4];
            #pragma unroll
            for (int m = 0; m < 4; ++m)
                mma16(oacc[m][nt], A[m*4],A[m*4+1],A[m*4+2],A[m*4+3], b0, b1);
        }
    }

    // O -> qtiles in Q region (Q dead after GEMM2)
    #pragma unroll
    for (int m = 0; m < 4; ++m)
        #pragma unroll
        for (int nt = 0; nt < 4; ++nt) {
            int kg = wc*2 + (nt >> 1);
            *(uint2*)(Qb + (m*8+kg)*128 + (nt&1)*64 + i4*2) =
                make_uint2(h2u(oacc[m][nt][0], oacc[m][nt][1]),
                           h2u(oacc[m][nt][2], oacc[m][nt][3]));
        }
    __syncthreads();
    stageW(Wb, g_wprojB, tid);
    __syncthreads();

    // ============ GEMM4: out = O @ Wproj + b ============
    float acc[4][4][4];
    #pragma unroll
    for (int m = 0; m < 4; ++m)
        #pragma unroll
        for (int n = 0; n < 4; ++n)
            acc[m][n][0]=acc[m][n][1]=acc[m][n][2]=acc[m][n][3]=0.f;

    #pragma unroll
    for (int kg = 0; kg < 8; ++kg) {
        uint32_t A[16];
        #pragma unroll
        for (int m = 0; m < 4; ++m)
            ldAq(A + m*4, Qb, m, kg, 8, i4);
        #pragma unroll
        for (int nt = 0; nt < 4; ++nt) {
            uint2 b = *(const uint2*)(Wb + ((wc*4+nt)*8 + kg)*64 + i4*2);
            #pragma unroll
            for (int m = 0; m < 4; ++m)
                mma16(acc[m][nt], A[m*4],A[m*4+1],A[m*4+2],A[m*4+3], b.x, b.y);
        }
    }

    float* outw = out + (size_t)blockIdx.x * 64 * 128;
    #pragma unroll
    for (int m = 0; m < 4; ++m) {
        int r = m*16 + g;
        #pragma unroll
        for (int nt = 0; nt < 4; ++nt) {
            int j = nbase + nt*8 + 2*t;
            float b0 = __ldg(bproj + j), b1 = __ldg(bproj + j + 1);
            *(float2*)(outw + r*128 + j)     = make_float2(acc[m][nt][0]+b0, acc[m][nt][1]+b1);
            *(float2*)(outw + (r+8)*128 + j) = make_float2(acc[m][nt][2]+b0, acc[m][nt][3]+b1);
        }
    }
}

extern "C" void kernel_launch(void* const* d_in, const int* in_sizes, int n_in,
                              void* d_out, int out_size)
{
    const float* x     = (const float*)d_in[0];
    const float* wqkv  = (const float*)d_in[1];
    const float* bqkv  = (const float*)d_in[2];
    const float* wproj = (const float*)d_in[3];
    const float* bproj = (const float*)d_in[4];
    float* out = (float*)d_out;

    const int nwin = in_sizes[0] / (64 * 128);   // 4096

    prep_w<<<512, 64>>>(wqkv, wproj);
    cudaFuncSetAttribute(win_attn_kernel,
                         cudaFuncAttributeMaxDynamicSharedMemorySize, SMEM_BYTES);
    win_attn_kernel<<<nwin, 128, SMEM_BYTES>>>(x, bqkv, bproj, out);
}

// round 16
// speedup vs baseline: 1.3075x; 1.0290x over previous
#include <cuda_runtime.h>
#include <cuda_fp16.h>
#include <cstdint>

// WindowAttention: 4096 x 64 x 128, fp32 I/O. fp16 operands, fp32 accum,
// mma.m16n8k16. R16 = R15 + (a) ring-buffered pipelined W staging (64-col
// halves, 3 slots; issue after slot-free barrier, wait after epilogue),
// (b) X in qtiles (GEMM1 A = 2x LDS.64), (c) K,V in btiles (B = 1x LDS.64).
// Smem 114688 B -> 2 CTAs/SM. 128 thr, 4 warps, 64x32 warp tiles.

#define OFF_X 0                  // X qtiles 4096 w; S(2048)+Pm(768) alias later
#define OFF_Q 4096               // Q/O qtiles 4096 w
#define OFF_K 8192               // K btiles 4096 w
#define OFF_V 12288              // V btiles 4096 w
#define OFF_W 16384              // W ring: 3 slots x 4096 w
#define OFF_S OFF_X
#define OFF_PM (OFF_X + 2048)
#define SMEM_WORDS 28672
#define SMEM_BYTES (SMEM_WORDS*4)   // 114688

// weights pre-packed into 64-col-half btiles: [half][n8=8][kg=8][64w]
__device__ __align__(16) uint32_t g_wqkvB[6*4096];
__device__ __align__(16) uint32_t g_wprojB[2*4096];

__global__ void prep_w(const float* __restrict__ wqkv, const float* __restrict__ wproj) {
    int b = blockIdx.x;          // global output col (0..383 qkv, 384..511 proj)
    int wk = threadIdx.x;        // 0..63 k-word
    int kg = wk >> 3, wi = wk & 7;
    if (b < 384) {
        uint32_t off = (uint32_t)((b>>6)*4096 + (((b>>3)&7)*8 + kg)*64
                                 + ((b&7)*4 + (wi&3))*2 + (wi>>2));
        __half2 h = __floats2half2_rn(wqkv[(2*wk)*384 + b], wqkv[(2*wk+1)*384 + b]);
        g_wqkvB[off] = *reinterpret_cast<uint32_t*>(&h);
    } else {
        int n = b - 384;
        uint32_t off = (uint32_t)((n>>6)*4096 + (((n>>3)&7)*8 + kg)*64
                                 + ((n&7)*4 + (wi&3))*2 + (wi>>2));
        __half2 h = __floats2half2_rn(wproj[(2*wk)*128 + n], wproj[(2*wk+1)*128 + n]);
        g_wprojB[off] = *reinterpret_cast<uint32_t*>(&h);
    }
}

__device__ __forceinline__ uint32_t h2u(float a, float b) {
    __half2 h = __floats2half2_rn(a, b);
    return *reinterpret_cast<uint32_t*>(&h);
}
__device__ __forceinline__ void mma16(float acc[4], uint32_t a0, uint32_t a1,
                                      uint32_t a2, uint32_t a3, uint32_t b0, uint32_t b1) {
    asm volatile(
        "mma.sync.aligned.m16n8k16.row.col.f32.f16.f16.f32 "
        "{%0,%1,%2,%3}, {%4,%5,%6,%7}, {%8,%9}, {%0,%1,%2,%3};\n"
        : "+f"(acc[0]), "+f"(acc[1]), "+f"(acc[2]), "+f"(acc[3])
        : "r"(a0), "r"(a1), "r"(a2), "r"(a3), "r"(b0), "r"(b1));
}
// A fragment from qtile region: 2x LDS.64
__device__ __forceinline__ void ldAq(uint32_t a[4], const uint32_t* base,
                                     int m, int kg, int KG, int lane) {
    const uint2* p = (const uint2*)(base + (m*KG + kg)*128) + lane;
    uint2 lo = p[0], hi = p[32];
    a[0]=lo.x; a[1]=lo.y; a[2]=hi.x; a[3]=hi.y;
}
// stage one 4096-word half (flat) via cp.async; commit, NO wait
__device__ __forceinline__ void stageH(uint32_t* dst, const uint32_t* __restrict__ src, int tid) {
    uint32_t base = (uint32_t)__cvta_generic_to_shared(dst);
    #pragma unroll
    for (int it = 0; it < 8; ++it) {
        int idx = tid + it*128;
        asm volatile("cp.async.ca.shared.global [%0], [%1], 16;"
                     :: "r"(base + (uint32_t)idx*16u), "l"(src + idx*4) : "memory");
    }
    asm volatile("cp.async.commit_group;" ::: "memory");
}
#define CPWAIT1() asm volatile("cp.async.wait_group 1;" ::: "memory")
#define CPWAIT0() asm volatile("cp.async.wait_group 0;" ::: "memory")

__global__ void __launch_bounds__(128, 2)
win_attn_kernel(const float* __restrict__ x, const float* __restrict__ bqkv,
                const float* __restrict__ bproj, float* __restrict__ out)
{
    extern __shared__ uint32_t smw[];
    uint32_t* Xq = smw + OFF_X;
    uint32_t* Qb = smw + OFF_Q;   // qtiles; reused for O
    uint32_t* Kb = smw + OFF_K;
    uint32_t* Vb = smw + OFF_V;
    uint32_t* Wr = smw + OFF_W;
    uint32_t* Sb = smw + OFF_S;
    float*    Pm = (float*)(smw + OFF_PM);
    __half*   Ve = (__half*)Vb;

    const int tid = threadIdx.x, warp = tid >> 5, lane = tid & 31;
    const int g = lane >> 2, t = lane & 3;
    const int wc = warp;
    const int nbase = wc * 32;
    const float* xw = x + (size_t)blockIdx.x * 64 * 128;

    // ---- issue W halves h0,h1,h2 immediately (g0,g1,g2) ----
    stageH(Wr,          g_wqkvB,          tid);
    stageH(Wr + 4096,   g_wqkvB + 4096,   tid);
    stageH(Wr + 8192,   g_wqkvB + 2*4096, tid);

    // ---- prologue: X fp32 -> qtiles (warp = m, lane = i4) ----
    {
        const float* xr0 = xw + (warp*16 + g)*128;
        const float* xr1 = xr0 + 8*128;
        #pragma unroll
        for (int kg = 0; kg < 8; ++kg) {
            int c0 = kg*16 + 2*t;
            float2 a0 = *(const float2*)(xr0 + c0);
            float2 b0 = *(const float2*)(xr1 + c0);
            float2 a1 = *(const float2*)(xr0 + c0 + 8);
            float2 b1 = *(const float2*)(xr1 + c0 + 8);
            uint32_t* e = Xq + (warp*8 + kg)*128 + lane*2;
            *(uint2*)e      = make_uint2(h2u(a0.x,a0.y), h2u(b0.x,b0.y));
            *(uint2*)(e+64) = make_uint2(h2u(a1.x,a1.y), h2u(b1.x,b1.y));
        }
    }
    CPWAIT1();          // g0,g1 done (g2 may pend)
    __syncthreads();

    // ============ GEMM1: QKV = X @ Wqkv + b (3 chunks of 128 cols) ============
    #pragma unroll
    for (int c = 0; c < 3; ++c) {
        const uint32_t* Wb = Wr + ((2*c + (wc>>1)) % 3) * 4096;
        float acc[4][4][4];
        #pragma unroll
        for (int m = 0; m < 4; ++m)
            #pragma unroll
            for (int n = 0; n < 4; ++n)
                acc[m][n][0]=acc[m][n][1]=acc[m][n][2]=acc[m][n][3]=0.f;

        #pragma unroll
        for (int kg = 0; kg < 8; ++kg) {
            uint32_t A[16];
            #pragma unroll
            for (int m = 0; m < 4; ++m)
                ldAq(A + m*4, Xq, m, kg, 8, lane);
            #pragma unroll
            for (int nt = 0; nt < 4; ++nt) {
                uint2 b = *(const uint2*)(Wb + (((wc&1)*4+nt)*8 + kg)*64 + lane*2);
                #pragma unroll
                for (int m = 0; m < 4; ++m)
                    mma16(acc[m][nt], A[m*4],A[m*4+1],A[m*4+2],A[m*4+3], b.x, b.y);
            }
        }

        __syncthreads();    // this chunk's ring slots are now free
        if (c == 0) {       // g3: h3->s0, g4: h4->s1
            stageH(Wr,        g_wqkvB + 3*4096, tid);
            stageH(Wr + 4096, g_wqkvB + 4*4096, tid);
        } else if (c == 1) {// g5: h5->s2, g6: proj0->s0
            stageH(Wr + 8192, g_wqkvB + 5*4096, tid);
            stageH(Wr,        g_wprojB,         tid);
        } else {            // g7: proj1->s1
            stageH(Wr + 4096, g_wprojB + 4096,  tid);
        }

        // ---- epilogue (hides the just-issued staging latency) ----
        if (c == 0) {        // Q -> qtiles
            #pragma unroll
            for (int m = 0; m < 4; ++m)
                #pragma unroll
                for (int nt = 0; nt < 4; ++nt) {
                    int j = nbase + nt*8 + 2*t;
                    float b0 = __ldg(bqkv + j), b1 = __ldg(bqkv + j + 1);
                    int kgq = wc*2 + (nt >> 1);
                    *(uint2*)(Qb + (m*8+kgq)*128 + (nt&1)*64 + lane*2) =
                        make_uint2(h2u(acc[m][nt][0]+b0, acc[m][nt][1]+b1),
                                   h2u(acc[m][nt][2]+b0, acc[m][nt][3]+b1));
                }
        } else if (c == 1) { // K -> btiles
            int wch = wc*16 + t;   // + nt*4 below
            #pragma unroll
            for (int m = 0; m < 4; ++m)
                #pragma unroll
                for (int nt = 0; nt < 4; ++nt) {
                    int j = nbase + nt*8 + 2*t;
                    float b0 = __ldg(bqkv + 128 + j), b1 = __ldg(bqkv + 128 + j + 1);
                    int w = wch + nt*4;
                    int kgc = w >> 3, wi = w & 7;
                    int eo = kgc*64 + ((g*4 + (wi&3))*2) + (wi>>2);
                    Kb[(2*m)*512   + eo] = h2u(acc[m][nt][0]+b0, acc[m][nt][1]+b1);
                    Kb[(2*m+1)*512 + eo] = h2u(acc[m][nt][2]+b0, acc[m][nt][3]+b1);
                }
        } else {             // V -> btiles (half scatter)
            #pragma unroll
            for (int m = 0; m < 4; ++m)
                #pragma unroll
                for (int nt = 0; nt < 4; ++nt) {
                    int ch = nbase + nt*8 + 2*t;
                    float b0 = __ldg(bqkv + 256 + ch), b1 = __ldg(bqkv + 256 + ch + 1);
                    int n8 = wc*4 + nt;
                    int w00 = (n8*4 + m)*64 + ((2*t)*4   + (g>>1))*2;
                    int w10 = (n8*4 + m)*64 + ((2*t+1)*4 + (g>>1))*2;
                    Ve[(w00)*2   + (g&1)] = __float2half_rn(acc[m][nt][0] + b0);
                    Ve[(w10)*2   + (g&1)] = __float2half_rn(acc[m][nt][1] + b1);
                    Ve[(w00+1)*2 + (g&1)] = __float2half_rn(acc[m][nt][2] + b0);
                    Ve[(w10+1)*2 + (g&1)] = __float2half_rn(acc[m][nt][3] + b1);
                }
        }

        if (c < 2) CPWAIT1();   // next chunk's two halves are done (one still allowed pending)
        __syncthreads();
    }

    // ============ GEMM2: S = Q @ K^T (64x16 per warp) ============
    float sacc[4][2][4];
    #pragma unroll
    for (int m = 0; m < 4; ++m)
        #pragma unroll
        for (int n = 0; n < 2; ++n)
            sacc[m][n][0]=sacc[m][n][1]=sacc[m][n][2]=sacc[m][n][3]=0.f;

    #pragma unroll
    for (int kg = 0; kg < 8; ++kg) {
        uint32_t A[16];
        #pragma unroll
        for (int m = 0; m < 4; ++m)
            ldAq(A + m*4, Qb, m, kg, 8, lane);
        #pragma unroll
        for (int nt = 0; nt < 2; ++nt) {
            uint2 b = *(const uint2*)(Kb + ((wc*2+nt)*8 + kg)*64 + lane*2);
            #pragma unroll
            for (int m = 0; m < 4; ++m)
                mma16(sacc[m][nt], A[m*4],A[m*4+1],A[m*4+2],A[m*4+3], b.x, b.y);
        }
    }

    // ---- softmax: each row spans all 4 warps (16 cols each) ----
    const float scale = 0.08838834764831844f;
    float mx[4][2];
    #pragma unroll
    for (int m = 0; m < 4; ++m) {
        mx[m][0] = -1e30f; mx[m][1] = -1e30f;
        #pragma unroll
        for (int n = 0; n < 2; ++n) {
            #pragma unroll
            for (int q = 0; q < 4; ++q) sacc[m][n][q] *= scale;
            mx[m][0] = fmaxf(mx[m][0], fmaxf(sacc[m][n][0], sacc[m][n][1]));
            mx[m][1] = fmaxf(mx[m][1], fmaxf(sacc[m][n][2], sacc[m][n][3]));
        }
    }
    #pragma unroll
    for (int m = 0; m < 4; ++m)
        #pragma unroll
        for (int h = 0; h < 2; ++h) {
            mx[m][h] = fmaxf(mx[m][h], __shfl_xor_sync(~0u, mx[m][h], 1));
            mx[m][h] = fmaxf(mx[m][h], __shfl_xor_sync(~0u, mx[m][h], 2));
        }
    if (t == 0)
        #pragma unroll
        for (int m = 0; m < 4; ++m)
            #pragma unroll
            for (int h = 0; h < 2; ++h)
                Pm[(m*16 + h*8 + g)*4 + wc] = mx[m][h];
    __syncthreads();
    #pragma unroll
    for (int m = 0; m < 4; ++m)
        #pragma unroll
        for (int h = 0; h < 2; ++h) {
            const float* p = Pm + (m*16 + h*8 + g)*4;
            mx[m][h] = fmaxf(fmaxf(p[0], p[1]), fmaxf(p[2], p[3]));
        }

    float sm[4][2];
    #pragma unroll
    for (int m = 0; m < 4; ++m) { sm[m][0] = 0.f; sm[m][1] = 0.f; }
    #pragma unroll
    for (int m = 0; m < 4; ++m)
        #pragma unroll
        for (int n = 0; n < 2; ++n) {
            sacc[m][n][0] = __expf(sacc[m][n][0] - mx[m][0]);
            sacc[m][n][1] = __expf(sacc[m][n][1] - mx[m][0]);
            sacc[m][n][2] = __expf(sacc[m][n][2] - mx[m][1]);
            sacc[m][n][3] = __expf(sacc[m][n][3] - mx[m][1]);
            sm[m][0] += sacc[m][n][0] + sacc[m][n][1];
            sm[m][1] += sacc[m][n][2] + sacc[m][n][3];
        }
    #pragma unroll
    for (int m = 0; m < 4; ++m)
        #pragma unroll
        for (int h = 0; h < 2; ++h) {
            sm[m][h] += __shfl_xor_sync(~0u, sm[m][h], 1);
            sm[m][h] += __shfl_xor_sync(~0u, sm[m][h], 2);
        }
    if (t == 0)
        #pragma unroll
        for (int m = 0; m < 4; ++m)
            #pragma unroll
            for (int h = 0; h < 2; ++h)
                Pm[512 + (m*16 + h*8 + g)*4 + wc] = sm[m][h];
    __syncthreads();
    float rs[4][2];
    #pragma unroll
    for (int m = 0; m < 4; ++m)
        #pragma unroll
        for (int h = 0; h < 2; ++h) {
            const float* p = Pm + 512 + (m*16 + h*8 + g)*4;
            rs[m][h] = 1.f / (p[0] + p[1] + p[2] + p[3]);
        }

    // P -> S qtiles (S aliases X; X dead after GEMM1)
    #pragma unroll
    for (int m = 0; m < 4; ++m)
        #pragma unroll
        for (int nt = 0; nt < 2; ++nt) {
            *(uint2*)(Sb + (m*4+wc)*128 + nt*64 + lane*2) =
                make_uint2(h2u(sacc[m][nt][0]*rs[m][0], sacc[m][nt][1]*rs[m][0]),
                           h2u(sacc[m][nt][2]*rs[m][1], sacc[m][nt][3]*rs[m][1]));
        }
    __syncthreads();

    // ============ GEMM3: O = P @ Vt (64x32 per warp) ============
    float oacc[4][4][4];
    #pragma unroll
    for (int m = 0; m < 4; ++m)
        #pragma unroll
        for (int n = 0; n < 4; ++n)
            oacc[m][n][0]=oacc[m][n][1]=oacc[m][n][2]=oacc[m][n][3]=0.f;

    #pragma unroll
    for (int kg = 0; kg < 4; ++kg) {
        uint32_t A[16];
        #pragma unroll
        for (int m = 0; m < 4; ++m)
            ldAq(A + m*4, Sb, m, kg, 4, lane);
        #pragma unroll
        for (int nt = 0; nt < 4; ++nt) {
            uint2 b = *(const uint2*)(Vb + ((wc*4+nt)*4 + kg)*64 + lane*2);
            #pragma unroll
            for (int m = 0; m < 4; ++m)
                mma16(oacc[m][nt], A[m*4],A[m*4+1],A[m*4+2],A[m*4+3], b.x, b.y);
        }
    }

    // O -> qtiles in Q region (Q dead after GEMM2)
    #pragma unroll
    for (int m = 0; m < 4; ++m)
        #pragma unroll
        for (int nt = 0; nt < 4; ++nt) {
            int kgq = wc*2 + (nt >> 1);
            *(uint2*)(Qb + (m*8+kgq)*128 + (nt&1)*64 + lane*2) =
                make_uint2(h2u(oacc[m][nt][0], oacc[m][nt][1]),
                           h2u(oacc[m][nt][2], oacc[m][nt][3]));
        }
    CPWAIT0();          // proj halves (g6,g7) done — staged long ago
    __syncthreads();

    // ============ GEMM4: out = O @ Wproj + b ============
    float acc[4][4][4];
    #pragma unroll
    for (int m = 0; m < 4; ++m)
        #pragma unroll
        for (int n = 0; n < 4; ++n)
            acc[m][n][0]=acc[m][n][1]=acc[m][n][2]=acc[m][n][3]=0.f;

    {
        const uint32_t* Wb = Wr + (wc>>1) * 4096;   // proj0->s0 (warps 0,1), proj1->s1
        #pragma unroll
        for (int kg = 0; kg < 8; ++kg) {
            uint32_t A[16];
            #pragma unroll
            for (int m = 0; m < 4; ++m)
                ldAq(A + m*4, Qb, m, kg, 8, lane);
            #pragma unroll
            for (int nt = 0; nt < 4; ++nt) {
                uint2 b = *(const uint2*)(Wb + (((wc&1)*4+nt)*8 + kg)*64 + lane*2);
                #pragma unroll
                for (int m = 0; m < 4; ++m)
                    mma16(acc[m][nt], A[m*4],A[m*4+1],A[m*4+2],A[m*4+3], b.x, b.y);
            }
        }
    }

    float* outw = out + (size_t)blockIdx.x * 64 * 128;
    #pragma unroll
    for (int m = 0; m < 4; ++m) {
        int r = m*16 + g;
        #pragma unroll
        for (int nt = 0; nt < 4; ++nt) {
            int j = nbase + nt*8 + 2*t;
            float b0 = __ldg(bproj + j), b1 = __ldg(bproj + j + 1);
            *(float2*)(outw + r*128 + j)     = make_float2(acc[m][nt][0]+b0, acc[m][nt][1]+b1);
            *(float2*)(outw + (r+8)*128 + j) = make_float2(acc[m][nt][2]+b0, acc[m][nt][3]+b1);
        }
    }
}

extern "C" void kernel_launch(void* const* d_in, const int* in_sizes, int n_in,
                              void* d_out, int out_size)
{
    const float* x     = (const float*)d_in[0];
    const float* wqkv  = (const float*)d_in[1];
    const float* bqkv  = (const float*)d_in[2];
    const float* wproj = (const float*)d_in[3];
    const float* bproj = (const float*)d_in[4];
    float* out = (float*)d_out;

    const int nwin = in_sizes[0] / (64 * 128);   // 4096

    prep_w<<<512, 64>>>(wqkv, wproj);
    cudaFuncSetAttribute(win_attn_kernel,
                         cudaFuncAttributeMaxDynamicSharedMemorySize, SMEM_BYTES);
    win_attn_kernel<<<nwin, 128, SMEM_BYTES>>>(x, bqkv, bproj, out);
}

// round 17
// speedup vs baseline: 1.3735x; 1.0505x over previous
#include <cuda_runtime.h>
#include <cuda_fp16.h>
#include <cstdint>

// WindowAttention: 4096 x 64 x 128, fp32 I/O. fp16 operands, fp32 accum,
// mma.m16n8k16. R17 = R16 + GEMM1 chunks 0+1 fused into ONE A-load sweep
// (acc[2][4][4][4], ~190 regs, legal at 2 CTAs x 128 thr = 256 regs/thr).
// 4-slot W ring; V btiles alias slot0 after pass 1. Smem 114688 -> 2 CTAs/SM.

#define OFF_X 0                  // X qtiles 4096 w; S(2048)+Pm alias later
#define OFF_Q 4096               // Q/O qtiles 4096 w
#define OFF_K 8192               // K btiles 4096 w
#define OFF_W 12288              // W ring: 4 slots x 4096 w (s0..s3)
#define OFF_V OFF_W              // V btiles alias slot0 (after pass 1)
#define OFF_S OFF_X
#define OFF_PM (OFF_X + 2048)
#define SMEM_WORDS 28672
#define SMEM_BYTES (SMEM_WORDS*4)   // 114688

// weights pre-packed into 64-col-half btiles: [half][n8=8][kg=8][64w]
__device__ __align__(16) uint32_t g_wqkvB[6*4096];
__device__ __align__(16) uint32_t g_wprojB[2*4096];

__global__ void prep_w(const float* __restrict__ wqkv, const float* __restrict__ wproj) {
    int b = blockIdx.x;          // global output col (0..383 qkv, 384..511 proj)
    int wk = threadIdx.x;        // 0..63 k-word
    int kg = wk >> 3, wi = wk & 7;
    if (b < 384) {
        uint32_t off = (uint32_t)((b>>6)*4096 + (((b>>3)&7)*8 + kg)*64
                                 + ((b&7)*4 + (wi&3))*2 + (wi>>2));
        __half2 h = __floats2half2_rn(wqkv[(2*wk)*384 + b], wqkv[(2*wk+1)*384 + b]);
        g_wqkvB[off] = *reinterpret_cast<uint32_t*>(&h);
    } else {
        int n = b - 384;
        uint32_t off = (uint32_t)((n>>6)*4096 + (((n>>3)&7)*8 + kg)*64
                                 + ((n&7)*4 + (wi&3))*2 + (wi>>2));
        __half2 h = __floats2half2_rn(wproj[(2*wk)*128 + n], wproj[(2*wk+1)*128 + n]);
        g_wprojB[off] = *reinterpret_cast<uint32_t*>(&h);
    }
}

__device__ __forceinline__ uint32_t h2u(float a, float b) {
    __half2 h = __floats2half2_rn(a, b);
    return *reinterpret_cast<uint32_t*>(&h);
}
__device__ __forceinline__ void mma16(float acc[4], uint32_t a0, uint32_t a1,
                                      uint32_t a2, uint32_t a3, uint32_t b0, uint32_t b1) {
    asm volatile(
        "mma.sync.aligned.m16n8k16.row.col.f32.f16.f16.f32 "
        "{%0,%1,%2,%3}, {%4,%5,%6,%7}, {%8,%9}, {%0,%1,%2,%3};\n"
        : "+f"(acc[0]), "+f"(acc[1]), "+f"(acc[2]), "+f"(acc[3])
        : "r"(a0), "r"(a1), "r"(a2), "r"(a3), "r"(b0), "r"(b1));
}
// A fragment from qtile region: 2x LDS.64
__device__ __forceinline__ void ldAq(uint32_t a[4], const uint32_t* base,
                                     int m, int kg, int KG, int lane) {
    const uint2* p = (const uint2*)(base + (m*KG + kg)*128) + lane;
    uint2 lo = p[0], hi = p[32];
    a[0]=lo.x; a[1]=lo.y; a[2]=hi.x; a[3]=hi.y;
}
// stage one 4096-word half (flat) via cp.async; commit, NO wait
__device__ __forceinline__ void stageH(uint32_t* dst, const uint32_t* __restrict__ src, int tid) {
    uint32_t base = (uint32_t)__cvta_generic_to_shared(dst);
    #pragma unroll
    for (int it = 0; it < 8; ++it) {
        int idx = tid + it*128;
        asm volatile("cp.async.ca.shared.global [%0], [%1], 16;"
                     :: "r"(base + (uint32_t)idx*16u), "l"(src + idx*4) : "memory");
    }
    asm volatile("cp.async.commit_group;" ::: "memory");
}
#define CPWAIT1() asm volatile("cp.async.wait_group 1;" ::: "memory")
#define CPWAIT0() asm volatile("cp.async.wait_group 0;" ::: "memory")

__global__ void __launch_bounds__(128, 2)
win_attn_kernel(const float* __restrict__ x, const float* __restrict__ bqkv,
                const float* __restrict__ bproj, float* __restrict__ out)
{
    extern __shared__ uint32_t smw[];
    uint32_t* Xq = smw + OFF_X;
    uint32_t* Qb = smw + OFF_Q;   // qtiles; reused for O
    uint32_t* Kb = smw + OFF_K;
    uint32_t* Wr = smw + OFF_W;
    uint32_t* Vb = smw + OFF_V;   // = slot0, valid after pass 1
    uint32_t* Sb = smw + OFF_S;
    float*    Pm = (float*)(smw + OFF_PM);
    __half*   Ve = (__half*)Vb;

    const int tid = threadIdx.x, warp = tid >> 5, lane = tid & 31;
    const int g = lane >> 2, t = lane & 3;
    const int wc = warp;
    const int nbase = wc * 32;
    const float* xw = x + (size_t)blockIdx.x * 64 * 128;

    // ---- issue h0..h3 (chunk0 + chunk1 halves) ----
    stageH(Wr,          g_wqkvB,          tid);
    stageH(Wr + 4096,   g_wqkvB + 4096,   tid);
    stageH(Wr + 8192,   g_wqkvB + 2*4096, tid);
    stageH(Wr + 12288,  g_wqkvB + 3*4096, tid);

    // ---- prologue: X fp32 -> qtiles (warp = m, lane = i4) ----
    {
        const float* xr0 = xw + (warp*16 + g)*128;
        const float* xr1 = xr0 + 8*128;
        #pragma unroll
        for (int kg = 0; kg < 8; ++kg) {
            int c0 = kg*16 + 2*t;
            float2 a0 = *(const float2*)(xr0 + c0);
            float2 b0 = *(const float2*)(xr1 + c0);
            float2 a1 = *(const float2*)(xr0 + c0 + 8);
            float2 b1 = *(const float2*)(xr1 + c0 + 8);
            uint32_t* e = Xq + (warp*8 + kg)*128 + lane*2;
            *(uint2*)e      = make_uint2(h2u(a0.x,a0.y), h2u(b0.x,b0.y));
            *(uint2*)(e+64) = make_uint2(h2u(a1.x,a1.y), h2u(b1.x,b1.y));
        }
    }
    CPWAIT0();
    __syncthreads();

    // ============ GEMM1 pass 1: chunks 0 (Q) + 1 (K) fused ============
    {
        const uint32_t* W0 = Wr + (wc>>1)*4096;          // chunk0 half
        const uint32_t* W1 = Wr + (2 + (wc>>1))*4096;    // chunk1 half
        float acc[2][4][4][4];
        #pragma unroll
        for (int c = 0; c < 2; ++c)
            #pragma unroll
            for (int m = 0; m < 4; ++m)
                #pragma unroll
                for (int n = 0; n < 4; ++n)
                    acc[c][m][n][0]=acc[c][m][n][1]=acc[c][m][n][2]=acc[c][m][n][3]=0.f;

        #pragma unroll
        for (int kg = 0; kg < 8; ++kg) {
            uint32_t A[16];
            #pragma unroll
            for (int m = 0; m < 4; ++m)
                ldAq(A + m*4, Xq, m, kg, 8, lane);
            #pragma unroll
            for (int nt = 0; nt < 4; ++nt) {
                uint2 b0 = *(const uint2*)(W0 + (((wc&1)*4+nt)*8 + kg)*64 + lane*2);
                uint2 b1 = *(const uint2*)(W1 + (((wc&1)*4+nt)*8 + kg)*64 + lane*2);
                #pragma unroll
                for (int m = 0; m < 4; ++m) {
                    mma16(acc[0][m][nt], A[m*4],A[m*4+1],A[m*4+2],A[m*4+3], b0.x, b0.y);
                    mma16(acc[1][m][nt], A[m*4],A[m*4+1],A[m*4+2],A[m*4+3], b1.x, b1.y);
                }
            }
        }

        __syncthreads();    // all warps done reading s0..s3
        stageH(Wr + 4096,  g_wqkvB + 4*4096, tid);   // h4 -> s1
        stageH(Wr + 8192,  g_wqkvB + 5*4096, tid);   // h5 -> s2
        stageH(Wr + 12288, g_wprojB,         tid);   // p0 -> s3

        // epilogue chunk0: Q -> qtiles
        #pragma unroll
        for (int m = 0; m < 4; ++m)
            #pragma unroll
            for (int nt = 0; nt < 4; ++nt) {
                int j = nbase + nt*8 + 2*t;
                float b0 = __ldg(bqkv + j), b1 = __ldg(bqkv + j + 1);
                int kgq = wc*2 + (nt >> 1);
                *(uint2*)(Qb + (m*8+kgq)*128 + (nt&1)*64 + lane*2) =
                    make_uint2(h2u(acc[0][m][nt][0]+b0, acc[0][m][nt][1]+b1),
                               h2u(acc[0][m][nt][2]+b0, acc[0][m][nt][3]+b1));
            }
        // epilogue chunk1: K -> btiles
        {
            int wch = wc*16 + t;
            #pragma unroll
            for (int m = 0; m < 4; ++m)
                #pragma unroll
                for (int nt = 0; nt < 4; ++nt) {
                    int j = nbase + nt*8 + 2*t;
                    float b0 = __ldg(bqkv + 128 + j), b1 = __ldg(bqkv + 128 + j + 1);
                    int w = wch + nt*4;
                    int kgc = w >> 3, wi = w & 7;
                    int eo = kgc*64 + ((g*4 + (wi&3))*2) + (wi>>2);
                    Kb[(2*m)*512   + eo] = h2u(acc[1][m][nt][0]+b0, acc[1][m][nt][1]+b1);
                    Kb[(2*m+1)*512 + eo] = h2u(acc[1][m][nt][2]+b0, acc[1][m][nt][3]+b1);
                }
        }
        CPWAIT1();      // h4,h5 done (p0 may pend)
        __syncthreads();
    }

    // ============ GEMM1 pass 2: chunk 2 (V) ============
    {
        const uint32_t* Wb = Wr + (1 + (wc>>1))*4096;    // s1 or s2
        float acc[4][4][4];
        #pragma unroll
        for (int m = 0; m < 4; ++m)
            #pragma unroll
            for (int n = 0; n < 4; ++n)
                acc[m][n][0]=acc[m][n][1]=acc[m][n][2]=acc[m][n][3]=0.f;

        #pragma unroll
        for (int kg = 0; kg < 8; ++kg) {
            uint32_t A[16];
            #pragma unroll
            for (int m = 0; m < 4; ++m)
                ldAq(A + m*4, Xq, m, kg, 8, lane);
            #pragma unroll
            for (int nt = 0; nt < 4; ++nt) {
                uint2 b = *(const uint2*)(Wb + (((wc&1)*4+nt)*8 + kg)*64 + lane*2);
                #pragma unroll
                for (int m = 0; m < 4; ++m)
                    mma16(acc[m][nt], A[m*4],A[m*4+1],A[m*4+2],A[m*4+3], b.x, b.y);
            }
        }
        __syncthreads();    // s1 reads done (and X reads done -> S alias safe)
        stageH(Wr + 4096, g_wprojB + 4096, tid);   // p1 -> s1

        // epilogue: V -> btiles at slot0
        #pragma unroll
        for (int m = 0; m < 4; ++m)
            #pragma unroll
            for (int nt = 0; nt < 4; ++nt) {
                int ch = nbase + nt*8 + 2*t;
                float b0 = __ldg(bqkv + 256 + ch), b1 = __ldg(bqkv + 256 + ch + 1);
                int n8 = wc*4 + nt;
                int w00 = (n8*4 + m)*64 + ((2*t)*4   + (g>>1))*2;
                int w10 = (n8*4 + m)*64 + ((2*t+1)*4 + (g>>1))*2;
                Ve[(w00)*2   + (g&1)] = __float2half_rn(acc[m][nt][0] + b0);
                Ve[(w10)*2   + (g&1)] = __float2half_rn(acc[m][nt][1] + b1);
                Ve[(w00+1)*2 + (g&1)] = __float2half_rn(acc[m][nt][2] + b0);
                Ve[(w10+1)*2 + (g&1)] = __float2half_rn(acc[m][nt][3] + b1);
            }
        __syncthreads();
    }

    // ============ GEMM2: S = Q @ K^T (64x16 per warp) ============
    float sacc[4][2][4];
    #pragma unroll
    for (int m = 0; m < 4; ++m)
        #pragma unroll
        for (int n = 0; n < 2; ++n)
            sacc[m][n][0]=sacc[m][n][1]=sacc[m][n][2]=sacc[m][n][3]=0.f;

    #pragma unroll
    for (int kg = 0; kg < 8; ++kg) {
        uint32_t A[16];
        #pragma unroll
        for (int m = 0; m < 4; ++m)
            ldAq(A + m*4, Qb, m, kg, 8, lane);
        #pragma unroll
        for (int nt = 0; nt < 2; ++nt) {
            uint2 b = *(const uint2*)(Kb + ((wc*2+nt)*8 + kg)*64 + lane*2);
            #pragma unroll
            for (int m = 0; m < 4; ++m)
                mma16(sacc[m][nt], A[m*4],A[m*4+1],A[m*4+2],A[m*4+3], b.x, b.y);
        }
    }

    // ---- softmax: each row spans all 4 warps (16 cols each) ----
    const float scale = 0.08838834764831844f;
    float mx[4][2];
    #pragma unroll
    for (int m = 0; m < 4; ++m) {
        mx[m][0] = -1e30f; mx[m][1] = -1e30f;
        #pragma unroll
        for (int n = 0; n < 2; ++n) {
            #pragma unroll
            for (int q = 0; q < 4; ++q) sacc[m][n][q] *= scale;
            mx[m][0] = fmaxf(mx[m][0], fmaxf(sacc[m][n][0], sacc[m][n][1]));
            mx[m][1] = fmaxf(mx[m][1], fmaxf(sacc[m][n][2], sacc[m][n][3]));
        }
    }
    #pragma unroll
    for (int m = 0; m < 4; ++m)
        #pragma unroll
        for (int h = 0; h < 2; ++h) {
            mx[m][h] = fmaxf(mx[m][h], __shfl_xor_sync(~0u, mx[m][h], 1));
            mx[m][h] = fmaxf(mx[m][h], __shfl_xor_sync(~0u, mx[m][h], 2));
        }
    if (t == 0)
        #pragma unroll
        for (int m = 0; m < 4; ++m)
            #pragma unroll
            for (int h = 0; h < 2; ++h)
                Pm[(m*16 + h*8 + g)*4 + wc] = mx[m][h];
    __syncthreads();
    #pragma unroll
    for (int m = 0; m < 4; ++m)
        #pragma unroll
        for (int h = 0; h < 2; ++h) {
            const float* p = Pm + (m*16 + h*8 + g)*4;
            mx[m][h] = fmaxf(fmaxf(p[0], p[1]), fmaxf(p[2], p[3]));
        }

    float sm[4][2];
    #pragma unroll
    for (int m = 0; m < 4; ++m) { sm[m][0] = 0.f; sm[m][1] = 0.f; }
    #pragma unroll
    for (int m = 0; m < 4; ++m)
        #pragma unroll
        for (int n = 0; n < 2; ++n) {
            sacc[m][n][0] = __expf(sacc[m][n][0] - mx[m][0]);
            sacc[m][n][1] = __expf(sacc[m][n][1] - mx[m][0]);
            sacc[m][n][2] = __expf(sacc[m][n][2] - mx[m][1]);
            sacc[m][n][3] = __expf(sacc[m][n][3] - mx[m][1]);
            sm[m][0] += sacc[m][n][0] + sacc[m][n][1];
            sm[m][1] += sacc[m][n][2] + sacc[m][n][3];
        }
    #pragma unroll
    for (int m = 0; m < 4; ++m)
        #pragma unroll
        for (int h = 0; h < 2; ++h) {
            sm[m][h] += __shfl_xor_sync(~0u, sm[m][h], 1);
            sm[m][h] += __shfl_xor_sync(~0u, sm[m][h], 2);
        }
    if (t == 0)
        #pragma unroll
        for (int m = 0; m < 4; ++m)
            #pragma unroll
            for (int h = 0; h < 2; ++h)
                Pm[512 + (m*16 + h*8 + g)*4 + wc] = sm[m][h];
    __syncthreads();
    float rs[4][2];
    #pragma unroll
    for (int m = 0; m < 4; ++m)
        #pragma unroll
        for (int h = 0; h < 2; ++h) {
            const float* p = Pm + 512 + (m*16 + h*8 + g)*4;
            rs[m][h] = 1.f / (p[0] + p[1] + p[2] + p[3]);
        }

    // P -> S qtiles (S aliases X; X dead after pass 2)
    #pragma unroll
    for (int m = 0; m < 4; ++m)
        #pragma unroll
        for (int nt = 0; nt < 2; ++nt) {
            *(uint2*)(Sb + (m*4+wc)*128 + nt*64 + lane*2) =
                make_uint2(h2u(sacc[m][nt][0]*rs[m][0], sacc[m][nt][1]*rs[m][0]),
                           h2u(sacc[m][nt][2]*rs[m][1], sacc[m][nt][3]*rs[m][1]));
        }
    __syncthreads();

    // ============ GEMM3: O = P @ Vt (64x32 per warp) ============
    float oacc[4][4][4];
    #pragma unroll
    for (int m = 0; m < 4; ++m)
        #pragma unroll
        for (int n = 0; n < 4; ++n)
            oacc[m][n][0]=oacc[m][n][1]=oacc[m][n][2]=oacc[m][n][3]=0.f;

    #pragma unroll
    for (int kg = 0; kg < 4; ++kg) {
        uint32_t A[16];
        #pragma unroll
        for (int m = 0; m < 4; ++m)
            ldAq(A + m*4, Sb, m, kg, 4, lane);
        #pragma unroll
        for (int nt = 0; nt < 4; ++nt) {
            uint2 b = *(const uint2*)(Vb + ((wc*4+nt)*4 + kg)*64 + lane*2);
            #pragma unroll
            for (int m = 0; m < 4; ++m)
                mma16(oacc[m][nt], A[m*4],A[m*4+1],A[m*4+2],A[m*4+3], b.x, b.y);
        }
    }

    // O -> qtiles in Q region (Q dead after GEMM2)
    #pragma unroll
    for (int m = 0; m < 4; ++m)
        #pragma unroll
        for (int nt = 0; nt < 4; ++nt) {
            int kgq = wc*2 + (nt >> 1);
            *(uint2*)(Qb + (m*8+kgq)*128 + (nt&1)*64 + lane*2) =
                make_uint2(h2u(oacc[m][nt][0], oacc[m][nt][1]),
                           h2u(oacc[m][nt][2], oacc[m][nt][3]));
        }
    CPWAIT0();          // p0 (s3) and p1 (s1) staged long ago
    __syncthreads();

    // ============ GEMM4: out = O @ Wproj + b ============
    float acc[4][4][4];
    #pragma unroll
    for (int m = 0; m < 4; ++m)
        #pragma unroll
        for (int n = 0; n < 4; ++n)
            acc[m][n][0]=acc[m][n][1]=acc[m][n][2]=acc[m][n][3]=0.f;

    {
        const uint32_t* Wb = Wr + ((wc>>1) == 0 ? 12288 : 4096);  // p0@s3, p1@s1
        #pragma unroll
        for (int kg = 0; kg < 8; ++kg) {
            uint32_t A[16];
            #pragma unroll
            for (int m = 0; m < 4; ++m)
                ldAq(A + m*4, Qb, m, kg, 8, lane);
            #pragma unroll
            for (int nt = 0; nt < 4; ++nt) {
                uint2 b = *(const uint2*)(Wb + (((wc&1)*4+nt)*8 + kg)*64 + lane*2);
                #pragma unroll
                for (int m = 0; m < 4; ++m)
                    mma16(acc[m][nt], A[m*4],A[m*4+1],A[m*4+2],A[m*4+3], b.x, b.y);
            }
        }
    }

    float* outw = out + (size_t)blockIdx.x * 64 * 128;
    #pragma unroll
    for (int m = 0; m < 4; ++m) {
        int r = m*16 + g;
        #pragma unroll
        for (int nt = 0; nt < 4; ++nt) {
            int j = nbase + nt*8 + 2*t;
            float b0 = __ldg(bproj + j), b1 = __ldg(bproj + j + 1);
            *(float2*)(outw + r*128 + j)     = make_float2(acc[m][nt][0]+b0, acc[m][nt][1]+b1);
            *(float2*)(outw + (r+8)*128 + j) = make_float2(acc[m][nt][2]+b0, acc[m][nt][3]+b1);
        }
    }
}

extern "C" void kernel_launch(void* const* d_in, const int* in_sizes, int n_in,
                              void* d_out, int out_size)
{
    const float* x     = (const float*)d_in[0];
    const float* wqkv  = (const float*)d_in[1];
    const float* bqkv  = (const float*)d_in[2];
    const float* wproj = (const float*)d_in[3];
    const float* bproj = (const float*)d_in[4];
    float* out = (float*)d_out;

    const int nwin = in_sizes[0] / (64 * 128);   // 4096

    prep_w<<<512, 64>>>(wqkv, wproj);
    cudaFuncSetAttribute(win_attn_kernel,
                         cudaFuncAttributeMaxDynamicSharedMemorySize, SMEM_BYTES);
    win_attn_kernel<<<nwin, 128, SMEM_BYTES>>>(x, bqkv, bproj, out);
}